// round 3
// baseline (speedup 1.0000x reference)
#include <cuda_runtime.h>
#include <math.h>

// RotationalConv2D: B=4, H=W=128, C=16, F=32, K=5, stride=1 -> Ho=Wo=124
// out[b,oh,ow,f] = sum_{p,c} rot(patch(b,oh,ow))[p,c] * W[f,p,c] + bias[f]
//
// Block: 8x8 patch tile (64 patches), 256 threads.
// smem: input tile 12x12x16, per-patch cos/sin, rot chunk (5 positions = 80 k),
//       W transposed/blocked [k4][f][4].
// GEMM: warp lane = f (32 f), warp id = group of 8 patches; acc[8] in regs,
//       accumulated across 5 position-chunks.

#define NTHREADS 256
#define IT 12              // input tile dim (8 + K-1)
#define RSTR4 21           // rot chunk stride in float4 (84 floats, 80 used)
#define SMEM_FLOATS (2304 + 64 + 64 + 64*84 + 12800)   // 20608 floats = 82432 B

__global__ __launch_bounds__(NTHREADS, 2)
void rotconv_kernel(const float* __restrict__ in,
                    const float* __restrict__ Wg,
                    const float* __restrict__ bias,
                    float* __restrict__ out)
{
    extern __shared__ float smem[];
    float* inTile = smem;                 // 12*12*16 = 2304
    float* cosS   = inTile + 2304;        // 64
    float* sinS   = cosS + 64;            // 64
    float* rotS   = sinS + 64;            // 64*84 = 5376
    float* Wb     = rotS + 64*84;         // 100*32*4 = 12800

    const float4* inTile4 = (const float4*)inTile;
    float4*       inTile4w = (float4*)inTile;
    float4*       rotS4   = (float4*)rotS;
    const float4* Wb4     = (const float4*)Wb;

    const int tid   = threadIdx.x;
    const int tileX = blockIdx.x;     // 0..15
    const int tileY = blockIdx.y;     // 0..15
    const int img   = blockIdx.z;     // 0..3

    // ---------------- Phase 1: load input tile + W (transposed/blocked) ----------------
    {
        const float4* in4 = (const float4*)in;
        for (int i = tid; i < 144 * 4; i += NTHREADS) {
            int c4   = i & 3;
            int cell = i >> 2;                    // 0..143
            int y = cell / IT;
            int x = cell - y * IT;
            int gr = tileY * 8 + y; if (gr > 127) gr = 127;
            int gc = tileX * 8 + x; if (gc > 127) gc = 127;
            inTile4w[cell * 4 + c4] = in4[(((img * 128 + gr) * 128 + gc) * 16 >> 2) + c4];
        }
        // W given as [F][k] (k = pos*16 + c, 400 per f). Store blocked:
        // Wb[(k>>2)*128 + f*4 + (k&3)]  -> float4 read Wb4[k4*32 + f]
        for (int i = tid; i < 12800; i += NTHREADS) {
            int f = i / 400;
            int k = i - f * 400;
            Wb[(k >> 2) * 128 + f * 4 + (k & 3)] = Wg[i];
        }
    }
    __syncthreads();

    // ---------------- Phase 2: per-patch centroid -> angle (64 threads) ----------------
    if (tid < 64) {
        int mr = tid >> 3, mc = tid & 7;
        float tot = 0.f, sr = 0.f, sc = 0.f;
        #pragma unroll
        for (int yy = 0; yy < 5; ++yy) {
            #pragma unroll
            for (int xx = 0; xx < 5; ++xx) {
                const float4* p = inTile4 + ((mr + yy) * IT + (mc + xx)) * 4;
                float4 a = p[0], b = p[1], c = p[2], d = p[3];
                float s = (a.x + a.y + a.z + a.w) + (b.x + b.y + b.z + b.w)
                        + (c.x + c.y + c.z + c.w) + (d.x + d.y + d.z + d.w);
                tot += s;
                sr  += s * (float)yy;
                sc  += s * (float)xx;
            }
        }
        tot += 1e-7f;
        float cr = sr / tot - 2.0f;
        float cc = sc / tot - 2.0f + 1e-7f;
        float ang = atan2f(cr, cc);
        float si, co;
        sincosf(ang, &si, &co);
        cosS[tid] = co;
        sinS[tid] = si;
    }
    __syncthreads();

    const int f     = tid & 31;     // lane = output feature
    const int wrp   = tid >> 5;     // warp = group of 8 patches
    const int mbase = wrp * 8;
    float acc[8];
    #pragma unroll
    for (int i = 0; i < 8; ++i) acc[i] = 0.f;

    const float scale = 1.0f / (1.0f + 1e-7f);

    // ---------------- Phase 3: 5 chunks of {rotate 5 positions, partial GEMM} ---------
    for (int ch = 0; ch < 5; ++ch) {
        // rotate: tasks = 64 patches x 5 local positions
        for (int t = tid; t < 320; t += NTHREADS) {
            int m  = t / 5;
            int pl = t - m * 5;
            int pos = ch * 5 + pl;
            int gy = pos / 5;
            int gx = pos - gy * 5;
            float co = cosS[m], si = sinS[m];
            float xoff = (4.0f - (co * 4.0f - si * 4.0f)) * 0.5f;
            float yoff = (4.0f - (si * 4.0f + co * 4.0f)) * 0.5f;
            float sx = (co * (float)gx - si * (float)gy + xoff) * scale;
            float sy = (si * (float)gx + co * (float)gy + yoff) * scale;
            float x0f = floorf(sx), y0f = floorf(sy);
            float wx = sx - x0f, wy = sy - y0f;
            int x0 = (int)x0f, y0 = (int)y0f;
            int x1 = x0 + 1,   y1 = y0 + 1;
            bool vx0 = (x0 >= 0) && (x0 < 5);
            bool vx1 = (x1 >= 0) && (x1 < 5);
            bool vy0 = (y0 >= 0) && (y0 < 5);
            bool vy1 = (y1 >= 0) && (y1 < 5);
            int x0c = x0 < 0 ? 0 : (x0 > 4 ? 4 : x0);
            int x1c = x1 < 0 ? 0 : (x1 > 4 ? 4 : x1);
            int y0c = y0 < 0 ? 0 : (y0 > 4 ? 4 : y0);
            int y1c = y1 < 0 ? 0 : (y1 > 4 ? 4 : y1);
            float w00 = (vx0 && vy0) ? (1.f - wx) * (1.f - wy) : 0.f;
            float w01 = (vx1 && vy0) ? wx * (1.f - wy)         : 0.f;
            float w10 = (vx0 && vy1) ? (1.f - wx) * wy         : 0.f;
            float w11 = (vx1 && vy1) ? wx * wy                 : 0.f;

            int mr = m >> 3, mc = m & 7;
            const float4* p00 = inTile4 + ((mr + y0c) * IT + (mc + x0c)) * 4;
            const float4* p01 = inTile4 + ((mr + y0c) * IT + (mc + x1c)) * 4;
            const float4* p10 = inTile4 + ((mr + y1c) * IT + (mc + x0c)) * 4;
            const float4* p11 = inTile4 + ((mr + y1c) * IT + (mc + x1c)) * 4;
            float4* dst = rotS4 + m * RSTR4 + pl * 4;
            #pragma unroll
            for (int cc4 = 0; cc4 < 4; ++cc4) {
                float4 a = p00[cc4], b = p01[cc4], c = p10[cc4], d = p11[cc4];
                float4 r;
                r.x = fmaf(a.x, w00, fmaf(b.x, w01, fmaf(c.x, w10, d.x * w11)));
                r.y = fmaf(a.y, w00, fmaf(b.y, w01, fmaf(c.y, w10, d.y * w11)));
                r.z = fmaf(a.z, w00, fmaf(b.z, w01, fmaf(c.z, w10, d.z * w11)));
                r.w = fmaf(a.w, w00, fmaf(b.w, w01, fmaf(c.w, w10, d.w * w11)));
                dst[cc4] = r;
            }
        }
        __syncthreads();

        // partial GEMM over this chunk's 80 k-values (20 float4 steps)
        const float4* WbC = Wb4 + ch * 20 * 32;
        #pragma unroll 4
        for (int k4 = 0; k4 < 20; ++k4) {
            float4 wv = WbC[k4 * 32 + f];
            #pragma unroll
            for (int i = 0; i < 8; ++i) {
                float4 rv = rotS4[(mbase + i) * RSTR4 + k4];
                acc[i] = fmaf(rv.x, wv.x,
                         fmaf(rv.y, wv.y,
                         fmaf(rv.z, wv.z,
                         fmaf(rv.w, wv.w, acc[i]))));
            }
        }
        __syncthreads();   // before next chunk overwrites rotS
    }

    // ---------------- Phase 4: write out ----------------
    const float bf = bias[f];
    #pragma unroll
    for (int i = 0; i < 8; ++i) {
        int m  = mbase + i;
        int mr = m >> 3, mc = m & 7;
        int oh = tileY * 8 + mr;
        int ow = tileX * 8 + mc;
        if (oh < 124 && ow < 124) {
            out[(((img * 124 + oh) * 124 + ow) << 5) + f] = acc[i] + bf;
        }
    }
}

extern "C" void kernel_launch(void* const* d_in, const int* in_sizes, int n_in,
                              void* d_out, int out_size)
{
    const float* in   = (const float*)d_in[0];   // [4,128,128,16]
    const float* Wg   = (const float*)d_in[1];   // [32,5,5,16]
    const float* bias = (const float*)d_in[2];   // [32]
    float* out = (float*)d_out;                  // [4,124,124,32]

    const int smem_bytes = SMEM_FLOATS * (int)sizeof(float);   // 82432
    cudaFuncSetAttribute(rotconv_kernel,
                         cudaFuncAttributeMaxDynamicSharedMemorySize, smem_bytes);

    dim3 grid(16, 16, 4);
    rotconv_kernel<<<grid, NTHREADS, smem_bytes>>>(in, Wg, bias, out);
}

// round 4
// speedup vs baseline: 1.7563x; 1.7563x over previous
#include <cuda_runtime.h>
#include <math.h>

// RotationalConv2D: B=4, H=W=128, C=16, F=32, K=5 -> Ho=Wo=124
// Block: 16x16 patch tile (256 patches), 256 threads, 2 blocks/SM.
// Thread GEMM tile: 4 patches x 8 features, accumulated as f32x2 pairs (FFMA2).
// Rot values stored duplicated ({v,v}) in smem so FFMA2 needs no packing MOVs.

#define FMA2(acc, a, b) asm("fma.rn.f32x2 %0, %1, %2, %0;" : "+l"(acc) : "l"(a), "l"(b))

#define NTHREADS 256
#define IT 20                 // input tile dim (16 + 4)
// smem (floats): inTile 20*20*16=6400 | rotD 256*36=9216 (chsum 400 aliased) | Wt 12800
#define SM_INTILE 0
#define SM_ROT    6400
#define SM_WT     15616
#define SMEM_FLOATS 28416     // 113664 bytes

__device__ float WtG[12800];  // W transposed to [k][f], k = pos*16+c

__global__ void transposeW_kernel(const float* __restrict__ Wg) {
    int i = blockIdx.x * 256 + threadIdx.x;      // Wg: [F=32][k=400]
    if (i < 12800) {
        int f = i / 400;
        int k = i - f * 400;
        WtG[k * 32 + f] = Wg[i];
    }
}

__global__ __launch_bounds__(NTHREADS, 2)
void rotconv_kernel(const float* __restrict__ in,
                    const float* __restrict__ bias,
                    float* __restrict__ out)
{
    extern __shared__ float smem[];
    float*  inTile  = smem + SM_INTILE;
    float*  rotD    = smem + SM_ROT;
    float*  chsum   = smem + SM_ROT;          // alias: used before rotD
    float*  Wts     = smem + SM_WT;

    const float4* inTile4  = (const float4*)inTile;
    float4*       inTile4w = (float4*)inTile;
    float4*       rotD4    = (float4*)rotD;
    const ulonglong2* rot2 = (const ulonglong2*)rotD;
    const ulonglong2* Wt2  = (const ulonglong2*)Wts;

    const int tid   = threadIdx.x;
    const int tileX = blockIdx.x;     // 0..7
    const int tileY = blockIdx.y;     // 0..7
    const int img   = blockIdx.z;     // 0..3

    // ---------- Phase 0: load input tile (20x20x16) + W into smem ----------
    {
        const float4* in4 = (const float4*)in;
        #pragma unroll 1
        for (int i = tid; i < 400 * 4; i += NTHREADS) {
            int c4   = i & 3;
            int cell = i >> 2;                 // 0..399
            int y = cell / IT;
            int x = cell - y * IT;
            int gr = tileY * 16 + y; if (gr > 127) gr = 127;
            int gc = tileX * 16 + x; if (gc > 127) gc = 127;
            inTile4w[cell * 4 + c4] = in4[((img * 128 + gr) * 128 + gc) * 4 + c4];
        }
        const float4* WtG4 = (const float4*)WtG;
        float4* Wts4 = (float4*)Wts;
        #pragma unroll 1
        for (int i = tid; i < 3200; i += NTHREADS) Wts4[i] = WtG4[i];
    }
    __syncthreads();

    // ---------- Phase 1: per-cell channel sums (20x20) ----------
    #pragma unroll 1
    for (int i = tid; i < 400; i += NTHREADS) {
        const float4* p = inTile4 + i * 4;
        float4 a = p[0], b = p[1], c = p[2], d = p[3];
        chsum[i] = (a.x + a.y + a.z + a.w) + (b.x + b.y + b.z + b.w)
                 + (c.x + c.y + c.z + c.w) + (d.x + d.y + d.z + d.w);
    }
    __syncthreads();

    // ---------- Phase 2: centroid -> angle for own patch (m = tid) ----------
    const int mr = tid >> 4;
    const int mc = tid & 15;
    float co, si;
    {
        float tot = 0.f, sr = 0.f, sc = 0.f;
        #pragma unroll
        for (int yy = 0; yy < 5; ++yy) {
            #pragma unroll
            for (int xx = 0; xx < 5; ++xx) {
                float s = chsum[(mr + yy) * IT + (mc + xx)];
                tot += s;
                sr  += s * (float)yy;
                sc  += s * (float)xx;
            }
        }
        tot += 1e-7f;
        float cr = sr / tot - 2.0f;
        float cc = sc / tot - 2.0f + 1e-7f;
        float ang = atan2f(cr, cc);
        sincosf(ang, &si, &co);
    }
    __syncthreads();   // centroid reads done before rotD (aliases chsum) is written

    const float scale = 1.0f / (1.0f + 1e-7f);
    const float xoff = (4.0f - (co * 4.0f - si * 4.0f)) * 0.5f;
    const float yoff = (4.0f - (si * 4.0f + co * 4.0f)) * 0.5f;

    const int fb2    = tid & 3;          // f-octet: f = fb2*8 .. +7
    const int pgbase = (tid >> 2) * 4;   // 4 patches: m = pgbase + i

    unsigned long long acc[4][4];
    #pragma unroll
    for (int i = 0; i < 4; ++i)
        #pragma unroll
        for (int j = 0; j < 4; ++j) acc[i][j] = 0ULL;

    // ---------- Phase 3: 25 position chunks: rotate 1 pos, partial GEMM ----------
    #pragma unroll 1
    for (int gy = 0; gy < 5; ++gy) {
        #pragma unroll 1
        for (int gx = 0; gx < 5; ++gx) {
            const int pos = gy * 5 + gx;

            // --- rotate own patch (m = tid) at this position, 16 channels ---
            {
                float sx = (co * (float)gx - si * (float)gy + xoff) * scale;
                float sy = (si * (float)gx + co * (float)gy + yoff) * scale;
                float x0f = floorf(sx), y0f = floorf(sy);
                float wx = sx - x0f, wy = sy - y0f;
                int x0 = (int)x0f, y0 = (int)y0f;
                int x1 = x0 + 1,   y1 = y0 + 1;
                bool vx0 = (x0 >= 0) && (x0 < 5);
                bool vx1 = (x1 >= 0) && (x1 < 5);
                bool vy0 = (y0 >= 0) && (y0 < 5);
                bool vy1 = (y1 >= 0) && (y1 < 5);
                int x0c = x0 < 0 ? 0 : (x0 > 4 ? 4 : x0);
                int x1c = x1 < 0 ? 0 : (x1 > 4 ? 4 : x1);
                int y0c = y0 < 0 ? 0 : (y0 > 4 ? 4 : y0);
                int y1c = y1 < 0 ? 0 : (y1 > 4 ? 4 : y1);
                float w00 = (vx0 && vy0) ? (1.f - wx) * (1.f - wy) : 0.f;
                float w01 = (vx1 && vy0) ? wx * (1.f - wy)         : 0.f;
                float w10 = (vx0 && vy1) ? (1.f - wx) * wy         : 0.f;
                float w11 = (vx1 && vy1) ? wx * wy                 : 0.f;

                const float4* p00 = inTile4 + ((mr + y0c) * IT + (mc + x0c)) * 4;
                const float4* p01 = inTile4 + ((mr + y0c) * IT + (mc + x1c)) * 4;
                const float4* p10 = inTile4 + ((mr + y1c) * IT + (mc + x0c)) * 4;
                const float4* p11 = inTile4 + ((mr + y1c) * IT + (mc + x1c)) * 4;
                float4* dst = rotD4 + tid * 9;
                #pragma unroll
                for (int c4 = 0; c4 < 4; ++c4) {
                    float4 a = p00[c4], b = p01[c4], c = p10[c4], d = p11[c4];
                    float4 r;
                    r.x = fmaf(a.x, w00, fmaf(b.x, w01, fmaf(c.x, w10, d.x * w11)));
                    r.y = fmaf(a.y, w00, fmaf(b.y, w01, fmaf(c.y, w10, d.y * w11)));
                    r.z = fmaf(a.z, w00, fmaf(b.z, w01, fmaf(c.z, w10, d.z * w11)));
                    r.w = fmaf(a.w, w00, fmaf(b.w, w01, fmaf(c.w, w10, d.w * w11)));
                    // duplicated pairs so GEMM loads f32x2 operands directly
                    dst[c4 * 2]     = make_float4(r.x, r.x, r.y, r.y);
                    dst[c4 * 2 + 1] = make_float4(r.z, r.z, r.w, r.w);
                }
            }
            __syncthreads();

            // --- partial GEMM over this position's 16 k-values ---
            #pragma unroll
            for (int k4l = 0; k4l < 4; ++k4l) {
                const int kb = pos * 16 + k4l * 4;
                ulonglong2 w0a = Wt2[(kb + 0) * 8 + fb2 * 2];
                ulonglong2 w0b = Wt2[(kb + 0) * 8 + fb2 * 2 + 1];
                ulonglong2 w1a = Wt2[(kb + 1) * 8 + fb2 * 2];
                ulonglong2 w1b = Wt2[(kb + 1) * 8 + fb2 * 2 + 1];
                ulonglong2 w2a = Wt2[(kb + 2) * 8 + fb2 * 2];
                ulonglong2 w2b = Wt2[(kb + 2) * 8 + fb2 * 2 + 1];
                ulonglong2 w3a = Wt2[(kb + 3) * 8 + fb2 * 2];
                ulonglong2 w3b = Wt2[(kb + 3) * 8 + fb2 * 2 + 1];
                #pragma unroll
                for (int i = 0; i < 4; ++i) {
                    const ulonglong2* rp = rot2 + (pgbase + i) * 9 + k4l * 2;
                    ulonglong2 ra = rp[0], rb = rp[1];
                    // kk=0 -> ra.x, kk=1 -> ra.y, kk=2 -> rb.x, kk=3 -> rb.y
                    FMA2(acc[i][0], ra.x, w0a.x); FMA2(acc[i][1], ra.x, w0a.y);
                    FMA2(acc[i][2], ra.x, w0b.x); FMA2(acc[i][3], ra.x, w0b.y);
                    FMA2(acc[i][0], ra.y, w1a.x); FMA2(acc[i][1], ra.y, w1a.y);
                    FMA2(acc[i][2], ra.y, w1b.x); FMA2(acc[i][3], ra.y, w1b.y);
                    FMA2(acc[i][0], rb.x, w2a.x); FMA2(acc[i][1], rb.x, w2a.y);
                    FMA2(acc[i][2], rb.x, w2b.x); FMA2(acc[i][3], rb.x, w2b.y);
                    FMA2(acc[i][0], rb.y, w3a.x); FMA2(acc[i][1], rb.y, w3a.y);
                    FMA2(acc[i][2], rb.y, w3b.x); FMA2(acc[i][3], rb.y, w3b.y);
                }
            }
            __syncthreads();   // before next position overwrites rotD
        }
    }

    // ---------- Phase 4: write out ----------
    {
        const float4* bias4 = (const float4*)bias;
        float4 bv0 = bias4[fb2 * 2];
        float4 bv1 = bias4[fb2 * 2 + 1];
        union { unsigned long long u; float2 f; } c0, c1, c2, c3;
        #pragma unroll
        for (int i = 0; i < 4; ++i) {
            int m  = pgbase + i;
            int pr = m >> 4, pc = m & 15;
            int oh = tileY * 16 + pr;
            int ow = tileX * 16 + pc;
            if (oh < 124 && ow < 124) {
                c0.u = acc[i][0]; c1.u = acc[i][1];
                c2.u = acc[i][2]; c3.u = acc[i][3];
                float4* ob = (float4*)(out + ((size_t)((img * 124 + oh) * 124 + ow)) * 32);
                ob[fb2 * 2]     = make_float4(c0.f.x + bv0.x, c0.f.y + bv0.y,
                                              c1.f.x + bv0.z, c1.f.y + bv0.w);
                ob[fb2 * 2 + 1] = make_float4(c2.f.x + bv1.x, c2.f.y + bv1.y,
                                              c3.f.x + bv1.z, c3.f.y + bv1.w);
            }
        }
    }
}

extern "C" void kernel_launch(void* const* d_in, const int* in_sizes, int n_in,
                              void* d_out, int out_size)
{
    const float* in   = (const float*)d_in[0];   // [4,128,128,16]
    const float* Wg   = (const float*)d_in[1];   // [32,5,5,16]
    const float* bias = (const float*)d_in[2];   // [32]
    float* out = (float*)d_out;                  // [4,124,124,32]

    transposeW_kernel<<<50, 256>>>(Wg);

    const int smem_bytes = SMEM_FLOATS * (int)sizeof(float);   // 113664
    cudaFuncSetAttribute(rotconv_kernel,
                         cudaFuncAttributeMaxDynamicSharedMemorySize, smem_bytes);
    dim3 grid(8, 8, 4);
    rotconv_kernel<<<grid, NTHREADS, smem_bytes>>>(in, bias, out);
}

// round 5
// speedup vs baseline: 2.8142x; 1.6024x over previous
#include <cuda_runtime.h>
#include <math.h>

// RotationalConv2D: B=4, H=W=128, C=16, F=32, K=5 -> Ho=Wo=124
// Block: 16x16 patch tile (256 patches), 256 threads, 2 blocks/SM.
// inTile stored as 4 channel-planes of float4 (conflict-free bilinear loads).
// Rot staged transposed: rotT[k][patch] -> GEMM loads natural patch-pairs for
// fma.rn.f32x2; W pre-duplicated {w,w} in global by a transpose kernel and
// staged per-5-position chunk (double buffered). One barrier per position.

#define FMA2(acc, a, b) asm("fma.rn.f32x2 %0, %1, %2, %0;" : "+l"(acc) : "l"(a), "l"(b))

#define NTHREADS 256
#define IT 20
// smem floats: planes 6400 | rotT 2*16*256=8192 (chsum 400 aliased in buf1) | Ws 2*5120=10240
#define SM_PLANES 0
#define SM_ROT    6400
#define SM_CHSUM  (6400 + 4096)      // alias rotT buffer 1
#define SM_WS     (6400 + 8192)
#define SMEM_FLOATS (6400 + 8192 + 10240)   // 24832 floats = 99328 B

// W duplicated+blocked: float idx = k*64 + part*32 + fq*4 + s*2 + d
// where f = fq*4 + part*2 + s, k = pos*16 + c, d in {0,1} duplicate.
__device__ float WdupG[25600];

__global__ void transposeW_kernel(const float* __restrict__ Wg) {
    int i = blockIdx.x * 256 + threadIdx.x;      // 0..25599
    if (i < 25600) {
        int k    = i >> 6;
        int r    = i & 63;
        int part = r >> 5;
        int r2   = r & 31;
        int fq   = r2 >> 2;
        int s    = (r2 & 3) >> 1;
        int f    = fq * 4 + part * 2 + s;
        WdupG[i] = Wg[f * 400 + k];
    }
}

__global__ __launch_bounds__(NTHREADS, 2)
void rotconv_kernel(const float* __restrict__ in,
                    const float* __restrict__ bias,
                    float* __restrict__ out)
{
    extern __shared__ float smem[];
    float4*           planes4 = (float4*)(smem + SM_PLANES);
    float*            rotT    = smem + SM_ROT;
    float*            chsum   = smem + SM_CHSUM;
    float*            Ws      = smem + SM_WS;
    float4*           Ws4     = (float4*)Ws;
    const ulonglong2* Ws2     = (const ulonglong2*)Ws;
    const ulonglong2* rot2    = (const ulonglong2*)rotT;

    const int tid   = threadIdx.x;
    const int tileX = blockIdx.x;     // 0..7
    const int tileY = blockIdx.y;     // 0..7
    const int img   = blockIdx.z;     // 0..3

    // ---------- Phase 0: load input tile into planes + stage W chunk 0 ----------
    {
        const float4* in4 = (const float4*)in;
        #pragma unroll 1
        for (int cell = tid; cell < 400; cell += NTHREADS) {
            int y = cell / IT;
            int x = cell - y * IT;
            int gr = tileY * 16 + y; if (gr > 127) gr = 127;
            int gc = tileX * 16 + x; if (gc > 127) gc = 127;
            const float4* src = in4 + ((img * 128 + gr) * 128 + gc) * 4;
            #pragma unroll
            for (int c4 = 0; c4 < 4; ++c4)
                planes4[c4 * 400 + cell] = src[c4];
        }
        const float4* Wd4 = (const float4*)WdupG;
        #pragma unroll 1
        for (int i = tid; i < 1280; i += NTHREADS) Ws4[i] = Wd4[i];
    }
    __syncthreads();

    // ---------- Phase 1: per-cell channel sums ----------
    #pragma unroll 1
    for (int cell = tid; cell < 400; cell += NTHREADS) {
        float4 a = planes4[cell], b = planes4[400 + cell],
               c = planes4[800 + cell], d = planes4[1200 + cell];
        chsum[cell] = (a.x + a.y + a.z + a.w) + (b.x + b.y + b.z + b.w)
                    + (c.x + c.y + c.z + c.w) + (d.x + d.y + d.z + d.w);
    }
    __syncthreads();

    // ---------- Phase 2: centroid -> angle (own patch m = tid) ----------
    const int mr = tid >> 4;
    const int mc = tid & 15;
    float co, si;
    {
        float tot = 0.f, sr = 0.f, sc = 0.f;
        #pragma unroll
        for (int yy = 0; yy < 5; ++yy) {
            #pragma unroll
            for (int xx = 0; xx < 5; ++xx) {
                float s = chsum[(mr + yy) * IT + (mc + xx)];
                tot += s;
                sr  += s * (float)yy;
                sc  += s * (float)xx;
            }
        }
        tot += 1e-7f;
        float cr = sr / tot - 2.0f;
        float cc = sc / tot - 2.0f + 1e-7f;
        float ang = atan2f(cr, cc);
        sincosf(ang, &si, &co);
    }
    // No barrier needed: first hazardous write (rotT buf1 at pos 1) is after sync_0.

    const float scale = 1.0f / (1.0f + 1e-7f);
    const float xoff = (4.0f - (co * 4.0f - si * 4.0f)) * 0.5f;
    const float yoff = (4.0f - (si * 4.0f + co * 4.0f)) * 0.5f;

    const int fq  = tid & 7;             // f quad: f = fq*4 .. +3
    const int pg2 = (tid >> 3) * 2;      // rot chunk idx: patches pgbase..pgbase+7
    const int pgbase = (tid >> 3) * 8;

    unsigned long long acc[4][4];        // [patch-pair][f-lane], each = {p_even, p_odd}
    #pragma unroll
    for (int i = 0; i < 4; ++i)
        #pragma unroll
        for (int j = 0; j < 4; ++j) acc[i][j] = 0ULL;

    // ---------- Phase 3: 25 positions: rotate -> sync -> partial GEMM ----------
    #pragma unroll 1
    for (int pos = 0; pos < 25; ++pos) {
        const int gy = pos / 5;
        const int gx = pos - gy * 5;
        float* buf = rotT + (pos & 1) * 4096;

        // --- rotate own patch at this position (16 channels) ---
        {
            float sx = (co * (float)gx - si * (float)gy + xoff) * scale;
            float sy = (si * (float)gx + co * (float)gy + yoff) * scale;
            float x0f = floorf(sx), y0f = floorf(sy);
            float wx = sx - x0f, wy = sy - y0f;
            int x0 = (int)x0f, y0 = (int)y0f;
            int x1 = x0 + 1,   y1 = y0 + 1;
            bool vx0 = (x0 >= 0) && (x0 < 5);
            bool vx1 = (x1 >= 0) && (x1 < 5);
            bool vy0 = (y0 >= 0) && (y0 < 5);
            bool vy1 = (y1 >= 0) && (y1 < 5);
            int x0c = x0 < 0 ? 0 : (x0 > 4 ? 4 : x0);
            int x1c = x1 < 0 ? 0 : (x1 > 4 ? 4 : x1);
            int y0c = y0 < 0 ? 0 : (y0 > 4 ? 4 : y0);
            int y1c = y1 < 0 ? 0 : (y1 > 4 ? 4 : y1);
            float w00 = (vx0 && vy0) ? (1.f - wx) * (1.f - wy) : 0.f;
            float w01 = (vx1 && vy0) ? wx * (1.f - wy)         : 0.f;
            float w10 = (vx0 && vy1) ? (1.f - wx) * wy         : 0.f;
            float w11 = (vx1 && vy1) ? wx * wy                 : 0.f;

            int cell00 = (mr + y0c) * IT + (mc + x0c);
            int cell01 = (mr + y0c) * IT + (mc + x1c);
            int cell10 = (mr + y1c) * IT + (mc + x0c);
            int cell11 = (mr + y1c) * IT + (mc + x1c);
            #pragma unroll
            for (int c4 = 0; c4 < 4; ++c4) {
                const float4* pl = planes4 + c4 * 400;
                float4 a = pl[cell00], b = pl[cell01], c = pl[cell10], d = pl[cell11];
                float rx = fmaf(a.x, w00, fmaf(b.x, w01, fmaf(c.x, w10, d.x * w11)));
                float ry = fmaf(a.y, w00, fmaf(b.y, w01, fmaf(c.y, w10, d.y * w11)));
                float rz = fmaf(a.z, w00, fmaf(b.z, w01, fmaf(c.z, w10, d.z * w11)));
                float rw = fmaf(a.w, w00, fmaf(b.w, w01, fmaf(c.w, w10, d.w * w11)));
                buf[(c4 * 4 + 0) * 256 + tid] = rx;
                buf[(c4 * 4 + 1) * 256 + tid] = ry;
                buf[(c4 * 4 + 2) * 256 + tid] = rz;
                buf[(c4 * 4 + 3) * 256 + tid] = rw;
            }
        }

        // --- prefetch 1/5 of next W chunk (no extra sync needed) ---
        if (pos < 20) {
            int nc = pos / 5 + 1;
            int sl = pos % 5;
            const float4* Wd4 = (const float4*)WdupG;
            Ws4[(nc & 1) * 1280 + sl * 256 + tid] = Wd4[nc * 1280 + sl * 256 + tid];
        }
        __syncthreads();

        // --- partial GEMM: 16 k-values of this position ---
        const ulonglong2* wp = Ws2 + ((pos / 5) & 1) * 1280 + (pos % 5) * 256;
        const ulonglong2* rp = rot2 + (pos & 1) * 1024;
        #pragma unroll
        for (int k = 0; k < 16; ++k) {
            ulonglong2 ra = rp[k * 64 + pg2];        // pairs {p0,p1},{p2,p3}
            ulonglong2 rb = rp[k * 64 + pg2 + 1];    // pairs {p4,p5},{p6,p7}
            ulonglong2 wA = wp[k * 16 + fq];         // splats f0, f1
            ulonglong2 wB = wp[k * 16 + 8 + fq];     // splats f2, f3
            FMA2(acc[0][0], ra.x, wA.x); FMA2(acc[0][1], ra.x, wA.y);
            FMA2(acc[0][2], ra.x, wB.x); FMA2(acc[0][3], ra.x, wB.y);
            FMA2(acc[1][0], ra.y, wA.x); FMA2(acc[1][1], ra.y, wA.y);
            FMA2(acc[1][2], ra.y, wB.x); FMA2(acc[1][3], ra.y, wB.y);
            FMA2(acc[2][0], rb.x, wA.x); FMA2(acc[2][1], rb.x, wA.y);
            FMA2(acc[2][2], rb.x, wB.x); FMA2(acc[2][3], rb.x, wB.y);
            FMA2(acc[3][0], rb.y, wA.x); FMA2(acc[3][1], rb.y, wA.y);
            FMA2(acc[3][2], rb.y, wB.x); FMA2(acc[3][3], rb.y, wB.y);
        }
        // next iteration's rotate writes the other buffer; one barrier per pos.
    }

    // ---------- Phase 4: write out ----------
    {
        const float4* bias4 = (const float4*)bias;
        float4 bv = bias4[fq];
        const int pr = pgbase >> 4;            // all 8 patches share the row
        const int oh = tileY * 16 + pr;
        union { unsigned long long u; float2 f; } u0, u1, u2, u3;
        #pragma unroll
        for (int pp = 0; pp < 4; ++pp) {
            u0.u = acc[pp][0]; u1.u = acc[pp][1];
            u2.u = acc[pp][2]; u3.u = acc[pp][3];
            int m0 = pgbase + pp * 2;
            int pc0 = m0 & 15;
            int ow0 = tileX * 16 + pc0;
            if (oh < 124) {
                if (ow0 < 124) {
                    float4* ob = (float4*)(out + ((size_t)((img * 124 + oh) * 124 + ow0)) * 32) + fq;
                    *ob = make_float4(u0.f.x + bv.x, u1.f.x + bv.y, u2.f.x + bv.z, u3.f.x + bv.w);
                }
                if (ow0 + 1 < 124) {
                    float4* ob = (float4*)(out + ((size_t)((img * 124 + oh) * 124 + ow0 + 1)) * 32) + fq;
                    *ob = make_float4(u0.f.y + bv.x, u1.f.y + bv.y, u2.f.y + bv.z, u3.f.y + bv.w);
                }
            }
        }
    }
}

extern "C" void kernel_launch(void* const* d_in, const int* in_sizes, int n_in,
                              void* d_out, int out_size)
{
    const float* in   = (const float*)d_in[0];   // [4,128,128,16]
    const float* Wg   = (const float*)d_in[1];   // [32,5,5,16]
    const float* bias = (const float*)d_in[2];   // [32]
    float* out = (float*)d_out;                  // [4,124,124,32]

    transposeW_kernel<<<100, 256>>>(Wg);

    const int smem_bytes = SMEM_FLOATS * (int)sizeof(float);   // 99328
    cudaFuncSetAttribute(rotconv_kernel,
                         cudaFuncAttributeMaxDynamicSharedMemorySize, smem_bytes);
    dim3 grid(8, 8, 4);
    rotconv_kernel<<<grid, NTHREADS, smem_bytes>>>(in, bias, out);
}

// round 8
// speedup vs baseline: 2.8254x; 1.0040x over previous
#include <cuda_runtime.h>
#include <math.h>

// RotationalConv2D: B=4,H=W=128,C=16,F=32,K=5 -> Ho=Wo=124  (scalar FFMA2 path)
// Block: 8x8 patch tile (64 patches), 128 threads, grid 16x16x4 = 1024 blocks,
// 38.4KB smem -> 5 resident blocks/SM (good balance across 6.9 blocks/SM).
// Rotate: thread = (patch, channel-half); writes rotT[k][patch] fp32 (1 wf STS).
// GEMM: thread = 4 patches x 4 f; rot loads natural patch-pairs (ulonglong2,
// 1 wf), W non-duplicated [k][f] rows (LDS.128, 1 wf), splat pairs via mov.b64.

#define FMA2(acc, a, b) asm("fma.rn.f32x2 %0, %1, %2, %0;" : "+l"(acc) : "l"(a), "l"(b))
#define SPLAT(p, w)     asm("mov.b64 %0, {%1, %1};" : "=l"(p) : "r"(w))

#define NTHREADS 128
// smem floats:
#define SM_PLANES 0         // 144 cells * 16 ch = 2304   (planes4[c4*144+cell])
#define SM_ROT    2304      // 2 * 16k * 64p = 2048       (chsum 144 aliases buf1)
#define SM_CHSUM  (2304 + 1024)
#define SM_COS    4352      // 64
#define SM_SIN    4416      // 64
#define SM_WS     4480      // 2 chunks * 80k * 32f = 5120
#define SMEM_FLOATS 9600    // 38400 B

__device__ float WkG[12800];   // W transposed: WkG[k*32 + f], k = pos*16 + c

__global__ void prepW_kernel(const float* __restrict__ Wg) {
    int i = blockIdx.x * 256 + threadIdx.x;   // 0..12799
    if (i < 12800) {
        int k = i >> 5;
        int f = i & 31;
        WkG[i] = Wg[f * 400 + k];
    }
}

__global__ __launch_bounds__(NTHREADS)
void rotconv_kernel(const float* __restrict__ in,
                    const float* __restrict__ bias,
                    float* __restrict__ out)
{
    extern __shared__ float smem[];
    float4*           planes4 = (float4*)(smem + SM_PLANES);
    float*            rotT    = smem + SM_ROT;
    float*            chsum   = smem + SM_CHSUM;
    float*            cosS    = smem + SM_COS;
    float*            sinS    = smem + SM_SIN;
    float4*           Ws4     = (float4*)(smem + SM_WS);
    const ulonglong2* rot2    = (const ulonglong2*)rotT;

    const int tid   = threadIdx.x;
    const int tileX = blockIdx.x;     // 0..15
    const int tileY = blockIdx.y;     // 0..15
    const int img   = blockIdx.z;     // 0..3

    // ---------- Phase 0: load input tile (12x12 cells) + W chunk 0 ----------
    {
        const float4* in4 = (const float4*)in;
        #pragma unroll 1
        for (int cell = tid; cell < 144; cell += NTHREADS) {
            int y = cell / 12;
            int x = cell - y * 12;
            int gr = tileY * 8 + y; if (gr > 127) gr = 127;
            int gc = tileX * 8 + x; if (gc > 127) gc = 127;
            const float4* src = in4 + ((img * 128 + gr) * 128 + gc) * 4;
            #pragma unroll
            for (int c4 = 0; c4 < 4; ++c4)
                planes4[c4 * 144 + cell] = src[c4];
        }
        const float4* Wk4 = (const float4*)WkG;
        #pragma unroll
        for (int j = 0; j < 5; ++j)
            Ws4[j * 128 + tid] = Wk4[j * 128 + tid];
    }
    __syncthreads();

    // ---------- Phase 1: per-cell channel sums ----------
    #pragma unroll 1
    for (int cell = tid; cell < 144; cell += NTHREADS) {
        float4 a = planes4[cell], b = planes4[144 + cell],
               c = planes4[288 + cell], d = planes4[432 + cell];
        chsum[cell] = (a.x + a.y + a.z + a.w) + (b.x + b.y + b.z + b.w)
                    + (c.x + c.y + c.z + c.w) + (d.x + d.y + d.z + d.w);
    }
    __syncthreads();

    // ---------- Phase 2: centroid -> angle (one thread per patch) ----------
    if (tid < 64) {
        int pr = tid >> 3, pc = tid & 7;
        float tot = 0.f, sr = 0.f, sc = 0.f;
        #pragma unroll
        for (int yy = 0; yy < 5; ++yy)
            #pragma unroll
            for (int xx = 0; xx < 5; ++xx) {
                float s = chsum[(pr + yy) * 12 + (pc + xx)];
                tot += s; sr += s * (float)yy; sc += s * (float)xx;
            }
        tot += 1e-7f;
        float cr = sr / tot - 2.0f;
        float cc = sc / tot - 2.0f + 1e-7f;
        float si, co;
        sincosf(atan2f(cr, cc), &si, &co);
        cosS[tid] = co;
        sinS[tid] = si;
    }
    __syncthreads();

    // rotate role: patch = tid&63, half h = tid>>6 (channels h*8..h*8+7)
    const int rpatch = tid & 63;
    const int h      = tid >> 6;
    const int rr     = rpatch >> 3;
    const int rc     = rpatch & 7;
    const float co = cosS[rpatch];
    const float si = sinS[rpatch];
    const float scale = 1.0f / (1.0f + 1e-7f);
    const float xoff = (4.0f - (co * 4.0f - si * 4.0f)) * 0.5f;
    const float yoff = (4.0f - (si * 4.0f + co * 4.0f)) * 0.5f;

    // GEMM role: fq = tid&7 (f = fq*4..+3), pg4 = tid>>3 (patches pg4*4..+3)
    const int fq  = tid & 7;
    const int pg4 = tid >> 3;

    unsigned long long acc[2][4];   // [patch-pair][f], pair = {p_even, p_odd}
    #pragma unroll
    for (int i = 0; i < 2; ++i)
        #pragma unroll
        for (int j = 0; j < 4; ++j) acc[i][j] = 0ULL;

    // ---------- Phase 3: 25 positions ----------
    #pragma unroll 1
    for (int pos = 0; pos < 25; ++pos) {
        const int gy = pos / 5;
        const int gx = pos - gy * 5;
        const int bufR = pos & 1;

        // --- rotate own (patch, channel-half) ---
        {
            float sx = (co * (float)gx - si * (float)gy + xoff) * scale;
            float sy = (si * (float)gx + co * (float)gy + yoff) * scale;
            float x0f = floorf(sx), y0f = floorf(sy);
            float wx = sx - x0f, wy = sy - y0f;
            int x0 = (int)x0f, y0 = (int)y0f;
            int x1 = x0 + 1,   y1 = y0 + 1;
            bool vx0 = (x0 >= 0) && (x0 < 5);
            bool vx1 = (x1 >= 0) && (x1 < 5);
            bool vy0 = (y0 >= 0) && (y0 < 5);
            bool vy1 = (y1 >= 0) && (y1 < 5);
            int x0c = x0 < 0 ? 0 : (x0 > 4 ? 4 : x0);
            int x1c = x1 < 0 ? 0 : (x1 > 4 ? 4 : x1);
            int y0c = y0 < 0 ? 0 : (y0 > 4 ? 4 : y0);
            int y1c = y1 < 0 ? 0 : (y1 > 4 ? 4 : y1);
            float w00 = (vx0 && vy0) ? (1.f - wx) * (1.f - wy) : 0.f;
            float w01 = (vx1 && vy0) ? wx * (1.f - wy)         : 0.f;
            float w10 = (vx0 && vy1) ? (1.f - wx) * wy         : 0.f;
            float w11 = (vx1 && vy1) ? wx * wy                 : 0.f;

            int cell00 = (rr + y0c) * 12 + (rc + x0c);
            int cell01 = (rr + y0c) * 12 + (rc + x1c);
            int cell10 = (rr + y1c) * 12 + (rc + x0c);
            int cell11 = (rr + y1c) * 12 + (rc + x1c);

            float* dstb = rotT + bufR * 1024 + rpatch;
            #pragma unroll
            for (int c4i = 0; c4i < 2; ++c4i) {
                const int c4 = h * 2 + c4i;
                const float4* pl = planes4 + c4 * 144;
                float4 a = pl[cell00], b = pl[cell01], c = pl[cell10], d = pl[cell11];
                float r0 = fmaf(a.x, w00, fmaf(b.x, w01, fmaf(c.x, w10, d.x * w11)));
                float r1 = fmaf(a.y, w00, fmaf(b.y, w01, fmaf(c.y, w10, d.y * w11)));
                float r2 = fmaf(a.z, w00, fmaf(b.z, w01, fmaf(c.z, w10, d.z * w11)));
                float r3 = fmaf(a.w, w00, fmaf(b.w, w01, fmaf(c.w, w10, d.w * w11)));
                dstb[(c4 * 4 + 0) * 64] = r0;
                dstb[(c4 * 4 + 1) * 64] = r1;
                dstb[(c4 * 4 + 2) * 64] = r2;
                dstb[(c4 * 4 + 3) * 64] = r3;
            }
        }

        // --- prefetch 1/5 of next W chunk ---
        if (pos < 20) {
            int nc = pos / 5 + 1;
            int sl = pos % 5;
            const float4* Wk4 = (const float4*)WkG;
            Ws4[(nc & 1) * 640 + sl * 128 + tid] = Wk4[nc * 640 + sl * 128 + tid];
        }
        __syncthreads();

        // --- partial GEMM: 16 k-values of this position ---
        const int lp = pos % 5;
        const float4*    wp = Ws4 + ((pos / 5) & 1) * 640 + lp * 128 + fq;
        const ulonglong2* rp = rot2 + bufR * 256 + pg4;
        #pragma unroll
        for (int k = 0; k < 16; ++k) {
            ulonglong2 ra = rp[k * 16];       // {p0,p1},{p2,p3}
            float4 wv = wp[k * 8];            // 4 f values
            unsigned long long pw0, pw1, pw2, pw3;
            SPLAT(pw0, __float_as_uint(wv.x));
            SPLAT(pw1, __float_as_uint(wv.y));
            SPLAT(pw2, __float_as_uint(wv.z));
            SPLAT(pw3, __float_as_uint(wv.w));
            FMA2(acc[0][0], ra.x, pw0); FMA2(acc[0][1], ra.x, pw1);
            FMA2(acc[0][2], ra.x, pw2); FMA2(acc[0][3], ra.x, pw3);
            FMA2(acc[1][0], ra.y, pw0); FMA2(acc[1][1], ra.y, pw1);
            FMA2(acc[1][2], ra.y, pw2); FMA2(acc[1][3], ra.y, pw3);
        }
        // next rotate writes the other rotT buffer; the pos+1 barrier orders
        // this GEMM's reads before pos+2's overwrite. One barrier per position.
    }

    // ---------- Phase 4: write out (4 patches x 4 f per thread) ----------
    {
        const float4* bias4 = (const float4*)bias;
        float4 bv = bias4[fq];
        union { unsigned long long u; float2 f; } u0, u1, u2, u3;
        #pragma unroll
        for (int pp = 0; pp < 2; ++pp) {
            u0.u = acc[pp][0]; u1.u = acc[pp][1];
            u2.u = acc[pp][2]; u3.u = acc[pp][3];
            int m0 = pg4 * 4 + pp * 2;         // patches m0, m0+1 (same tile row)
            int pr = m0 >> 3, pc = m0 & 7;
            int oh = tileY * 8 + pr;
            int ow = tileX * 8 + pc;
            if (oh < 124) {
                if (ow < 124) {
                    float4* ob = (float4*)(out + ((size_t)((img * 124 + oh) * 124 + ow)) * 32) + fq;
                    *ob = make_float4(u0.f.x + bv.x, u1.f.x + bv.y,
                                      u2.f.x + bv.z, u3.f.x + bv.w);
                }
                if (ow + 1 < 124) {
                    float4* ob = (float4*)(out + ((size_t)((img * 124 + oh) * 124 + ow + 1)) * 32) + fq;
                    *ob = make_float4(u0.f.y + bv.x, u1.f.y + bv.y,
                                      u2.f.y + bv.z, u3.f.y + bv.w);
                }
            }
        }
    }
}

extern "C" void kernel_launch(void* const* d_in, const int* in_sizes, int n_in,
                              void* d_out, int out_size)
{
    const float* in   = (const float*)d_in[0];   // [4,128,128,16]
    const float* Wg   = (const float*)d_in[1];   // [32,5,5,16]
    const float* bias = (const float*)d_in[2];   // [32]
    float* out = (float*)d_out;                  // [4,124,124,32]

    prepW_kernel<<<50, 256>>>(Wg);

    const int smem_bytes = SMEM_FLOATS * (int)sizeof(float);   // 38400
    cudaFuncSetAttribute(rotconv_kernel,
                         cudaFuncAttributeMaxDynamicSharedMemorySize, smem_bytes);
    dim3 grid(16, 16, 4);
    rotconv_kernel<<<grid, NTHREADS, smem_bytes>>>(in, bias, out);
}

// round 9
// speedup vs baseline: 2.8389x; 1.0048x over previous
#include <cuda_runtime.h>
#include <math.h>

// RotationalConv2D: B=4,H=W=128,C=16,F=32,K=5 -> Ho=Wo=124  (scalar FFMA2 path)
// Block: 8x8 patch tile (64 patches), 128 threads, grid 16x16x4 = 1024 blocks,
// 38.4KB smem -> 5 resident blocks/SM (good balance across 6.9 blocks/SM).
// Rotate: thread = (patch, channel-half); writes rotT[k][patch] fp32 (1 wf STS).
// GEMM: thread = 4 patches x 4 f; rot loads natural patch-pairs (ulonglong2,
// 1 wf), W non-duplicated [k][f] rows (LDS.128, 1 wf), splat pairs via mov.b64.

#define FMA2(acc, a, b) asm("fma.rn.f32x2 %0, %1, %2, %0;" : "+l"(acc) : "l"(a), "l"(b))
#define SPLAT(p, w)     asm("mov.b64 %0, {%1, %1};" : "=l"(p) : "r"(w))

#define NTHREADS 128
// smem floats:
#define SM_PLANES 0         // 144 cells * 16 ch = 2304   (planes4[c4*144+cell])
#define SM_ROT    2304      // 2 * 16k * 64p = 2048       (chsum 144 aliases buf1)
#define SM_CHSUM  (2304 + 1024)
#define SM_COS    4352      // 64
#define SM_SIN    4416      // 64
#define SM_WS     4480      // 2 chunks * 80k * 32f = 5120
#define SMEM_FLOATS 9600    // 38400 B

__device__ float WkG[12800];   // W transposed: WkG[k*32 + f], k = pos*16 + c

__global__ void prepW_kernel(const float* __restrict__ Wg) {
    int i = blockIdx.x * 256 + threadIdx.x;   // 0..12799
    if (i < 12800) {
        int k = i >> 5;
        int f = i & 31;
        WkG[i] = Wg[f * 400 + k];
    }
}

__global__ __launch_bounds__(NTHREADS)
void rotconv_kernel(const float* __restrict__ in,
                    const float* __restrict__ bias,
                    float* __restrict__ out)
{
    extern __shared__ float smem[];
    float4*           planes4 = (float4*)(smem + SM_PLANES);
    float*            rotT    = smem + SM_ROT;
    float*            chsum   = smem + SM_CHSUM;
    float*            cosS    = smem + SM_COS;
    float*            sinS    = smem + SM_SIN;
    float4*           Ws4     = (float4*)(smem + SM_WS);
    const ulonglong2* rot2    = (const ulonglong2*)rotT;

    const int tid   = threadIdx.x;
    const int tileX = blockIdx.x;     // 0..15
    const int tileY = blockIdx.y;     // 0..15
    const int img   = blockIdx.z;     // 0..3

    // ---------- Phase 0: load input tile (12x12 cells) + W chunk 0 ----------
    {
        const float4* in4 = (const float4*)in;
        #pragma unroll 1
        for (int cell = tid; cell < 144; cell += NTHREADS) {
            int y = cell / 12;
            int x = cell - y * 12;
            int gr = tileY * 8 + y; if (gr > 127) gr = 127;
            int gc = tileX * 8 + x; if (gc > 127) gc = 127;
            const float4* src = in4 + ((img * 128 + gr) * 128 + gc) * 4;
            #pragma unroll
            for (int c4 = 0; c4 < 4; ++c4)
                planes4[c4 * 144 + cell] = src[c4];
        }
        const float4* Wk4 = (const float4*)WkG;
        #pragma unroll
        for (int j = 0; j < 5; ++j)
            Ws4[j * 128 + tid] = Wk4[j * 128 + tid];
    }
    __syncthreads();

    // ---------- Phase 1: per-cell channel sums ----------
    #pragma unroll 1
    for (int cell = tid; cell < 144; cell += NTHREADS) {
        float4 a = planes4[cell], b = planes4[144 + cell],
               c = planes4[288 + cell], d = planes4[432 + cell];
        chsum[cell] = (a.x + a.y + a.z + a.w) + (b.x + b.y + b.z + b.w)
                    + (c.x + c.y + c.z + c.w) + (d.x + d.y + d.z + d.w);
    }
    __syncthreads();

    // ---------- Phase 2: centroid -> angle (one thread per patch) ----------
    if (tid < 64) {
        int pr = tid >> 3, pc = tid & 7;
        float tot = 0.f, sr = 0.f, sc = 0.f;
        #pragma unroll
        for (int yy = 0; yy < 5; ++yy)
            #pragma unroll
            for (int xx = 0; xx < 5; ++xx) {
                float s = chsum[(pr + yy) * 12 + (pc + xx)];
                tot += s; sr += s * (float)yy; sc += s * (float)xx;
            }
        tot += 1e-7f;
        float cr = sr / tot - 2.0f;
        float cc = sc / tot - 2.0f + 1e-7f;
        float si, co;
        sincosf(atan2f(cr, cc), &si, &co);
        cosS[tid] = co;
        sinS[tid] = si;
    }
    __syncthreads();

    // rotate role: patch = tid&63, half h = tid>>6 (channels h*8..h*8+7)
    const int rpatch = tid & 63;
    const int h      = tid >> 6;
    const int rr     = rpatch >> 3;
    const int rc     = rpatch & 7;
    const float co = cosS[rpatch];
    const float si = sinS[rpatch];
    const float scale = 1.0f / (1.0f + 1e-7f);
    const float xoff = (4.0f - (co * 4.0f - si * 4.0f)) * 0.5f;
    const float yoff = (4.0f - (si * 4.0f + co * 4.0f)) * 0.5f;

    // GEMM role: fq = tid&7 (f = fq*4..+3), pg4 = tid>>3 (patches pg4*4..+3)
    const int fq  = tid & 7;
    const int pg4 = tid >> 3;

    unsigned long long acc[2][4];   // [patch-pair][f], pair = {p_even, p_odd}
    #pragma unroll
    for (int i = 0; i < 2; ++i)
        #pragma unroll
        for (int j = 0; j < 4; ++j) acc[i][j] = 0ULL;

    // ---------- Phase 3: 25 positions ----------
    #pragma unroll 1
    for (int pos = 0; pos < 25; ++pos) {
        const int gy = pos / 5;
        const int gx = pos - gy * 5;
        const int bufR = pos & 1;

        // --- rotate own (patch, channel-half) ---
        {
            float sx = (co * (float)gx - si * (float)gy + xoff) * scale;
            float sy = (si * (float)gx + co * (float)gy + yoff) * scale;
            float x0f = floorf(sx), y0f = floorf(sy);
            float wx = sx - x0f, wy = sy - y0f;
            int x0 = (int)x0f, y0 = (int)y0f;
            int x1 = x0 + 1,   y1 = y0 + 1;
            bool vx0 = (x0 >= 0) && (x0 < 5);
            bool vx1 = (x1 >= 0) && (x1 < 5);
            bool vy0 = (y0 >= 0) && (y0 < 5);
            bool vy1 = (y1 >= 0) && (y1 < 5);
            int x0c = x0 < 0 ? 0 : (x0 > 4 ? 4 : x0);
            int x1c = x1 < 0 ? 0 : (x1 > 4 ? 4 : x1);
            int y0c = y0 < 0 ? 0 : (y0 > 4 ? 4 : y0);
            int y1c = y1 < 0 ? 0 : (y1 > 4 ? 4 : y1);
            float w00 = (vx0 && vy0) ? (1.f - wx) * (1.f - wy) : 0.f;
            float w01 = (vx1 && vy0) ? wx * (1.f - wy)         : 0.f;
            float w10 = (vx0 && vy1) ? (1.f - wx) * wy         : 0.f;
            float w11 = (vx1 && vy1) ? wx * wy                 : 0.f;

            int cell00 = (rr + y0c) * 12 + (rc + x0c);
            int cell01 = (rr + y0c) * 12 + (rc + x1c);
            int cell10 = (rr + y1c) * 12 + (rc + x0c);
            int cell11 = (rr + y1c) * 12 + (rc + x1c);

            float* dstb = rotT + bufR * 1024 + rpatch;
            #pragma unroll
            for (int c4i = 0; c4i < 2; ++c4i) {
                const int c4 = h * 2 + c4i;
                const float4* pl = planes4 + c4 * 144;
                float4 a = pl[cell00], b = pl[cell01], c = pl[cell10], d = pl[cell11];
                float r0 = fmaf(a.x, w00, fmaf(b.x, w01, fmaf(c.x, w10, d.x * w11)));
                float r1 = fmaf(a.y, w00, fmaf(b.y, w01, fmaf(c.y, w10, d.y * w11)));
                float r2 = fmaf(a.z, w00, fmaf(b.z, w01, fmaf(c.z, w10, d.z * w11)));
                float r3 = fmaf(a.w, w00, fmaf(b.w, w01, fmaf(c.w, w10, d.w * w11)));
                dstb[(c4 * 4 + 0) * 64] = r0;
                dstb[(c4 * 4 + 1) * 64] = r1;
                dstb[(c4 * 4 + 2) * 64] = r2;
                dstb[(c4 * 4 + 3) * 64] = r3;
            }
        }

        // --- prefetch 1/5 of next W chunk ---
        if (pos < 20) {
            int nc = pos / 5 + 1;
            int sl = pos % 5;
            const float4* Wk4 = (const float4*)WkG;
            Ws4[(nc & 1) * 640 + sl * 128 + tid] = Wk4[nc * 640 + sl * 128 + tid];
        }
        __syncthreads();

        // --- partial GEMM: 16 k-values of this position ---
        const int lp = pos % 5;
        const float4*    wp = Ws4 + ((pos / 5) & 1) * 640 + lp * 128 + fq;
        const ulonglong2* rp = rot2 + bufR * 256 + pg4;
        #pragma unroll
        for (int k = 0; k < 16; ++k) {
            ulonglong2 ra = rp[k * 16];       // {p0,p1},{p2,p3}
            float4 wv = wp[k * 8];            // 4 f values
            unsigned long long pw0, pw1, pw2, pw3;
            SPLAT(pw0, __float_as_uint(wv.x));
            SPLAT(pw1, __float_as_uint(wv.y));
            SPLAT(pw2, __float_as_uint(wv.z));
            SPLAT(pw3, __float_as_uint(wv.w));
            FMA2(acc[0][0], ra.x, pw0); FMA2(acc[0][1], ra.x, pw1);
            FMA2(acc[0][2], ra.x, pw2); FMA2(acc[0][3], ra.x, pw3);
            FMA2(acc[1][0], ra.y, pw0); FMA2(acc[1][1], ra.y, pw1);
            FMA2(acc[1][2], ra.y, pw2); FMA2(acc[1][3], ra.y, pw3);
        }
        // next rotate writes the other rotT buffer; the pos+1 barrier orders
        // this GEMM's reads before pos+2's overwrite. One barrier per position.
    }

    // ---------- Phase 4: write out (4 patches x 4 f per thread) ----------
    {
        const float4* bias4 = (const float4*)bias;
        float4 bv = bias4[fq];
        union { unsigned long long u; float2 f; } u0, u1, u2, u3;
        #pragma unroll
        for (int pp = 0; pp < 2; ++pp) {
            u0.u = acc[pp][0]; u1.u = acc[pp][1];
            u2.u = acc[pp][2]; u3.u = acc[pp][3];
            int m0 = pg4 * 4 + pp * 2;         // patches m0, m0+1 (same tile row)
            int pr = m0 >> 3, pc = m0 & 7;
            int oh = tileY * 8 + pr;
            int ow = tileX * 8 + pc;
            if (oh < 124) {
                if (ow < 124) {
                    float4* ob = (float4*)(out + ((size_t)((img * 124 + oh) * 124 + ow)) * 32) + fq;
                    *ob = make_float4(u0.f.x + bv.x, u1.f.x + bv.y,
                                      u2.f.x + bv.z, u3.f.x + bv.w);
                }
                if (ow + 1 < 124) {
                    float4* ob = (float4*)(out + ((size_t)((img * 124 + oh) * 124 + ow + 1)) * 32) + fq;
                    *ob = make_float4(u0.f.y + bv.x, u1.f.y + bv.y,
                                      u2.f.y + bv.z, u3.f.y + bv.w);
                }
            }
        }
    }
}

extern "C" void kernel_launch(void* const* d_in, const int* in_sizes, int n_in,
                              void* d_out, int out_size)
{
    const float* in   = (const float*)d_in[0];   // [4,128,128,16]
    const float* Wg   = (const float*)d_in[1];   // [32,5,5,16]
    const float* bias = (const float*)d_in[2];   // [32]
    float* out = (float*)d_out;                  // [4,124,124,32]

    prepW_kernel<<<50, 256>>>(Wg);

    const int smem_bytes = SMEM_FLOATS * (int)sizeof(float);   // 38400
    cudaFuncSetAttribute(rotconv_kernel,
                         cudaFuncAttributeMaxDynamicSharedMemorySize, smem_bytes);
    dim3 grid(16, 16, 4);
    rotconv_kernel<<<grid, NTHREADS, smem_bytes>>>(in, bias, out);
}